// round 5
// baseline (speedup 1.0000x reference)
#include <cuda_runtime.h>
#include <cstdint>

#define NUM_NODE 50000
#define NUM_EDGE 1600000
#define NUM_REL  512
#define DIM      64
#define SCAN_T   1024

// ---------------------------------------------------------------------------
// Device scratch (alloc-free rule: __device__ globals)
// ---------------------------------------------------------------------------
__device__ int   g_count[NUM_NODE];
__device__ int   g_cursor[NUM_NODE];
__device__ int   g_off[NUM_NODE + 1];
__device__ int4  g_meta[NUM_EDGE];        // (u, r, w_bits, unused) per bucket slot
__device__ float g_u[NUM_NODE * DIM];     // sqrt-variance result staged for GEMM

// ---------------------------------------------------------------------------
// K0: zero counters
// ---------------------------------------------------------------------------
__global__ void zero_kernel() {
    int i = blockIdx.x * blockDim.x + threadIdx.x;
    if (i < NUM_NODE) {
        g_count[i]  = 0;
        g_cursor[i] = 0;
    }
}

// ---------------------------------------------------------------------------
// K1: histogram of destination nodes
// ---------------------------------------------------------------------------
__global__ void __launch_bounds__(256) hist_kernel(const int* __restrict__ edge_list) {
    int e = blockIdx.x * blockDim.x + threadIdx.x;
    if (e < NUM_EDGE) {
        int v = __ldg(&edge_list[e * 3 + 1]);
        atomicAdd(&g_count[v], 1);
    }
}

// ---------------------------------------------------------------------------
// K2: single-block exclusive scan over 50K counts -> offsets
// ---------------------------------------------------------------------------
__global__ void __launch_bounds__(SCAN_T) scan_kernel() {
    __shared__ int partial[SCAN_T];
    const int CH = (NUM_NODE + SCAN_T - 1) / SCAN_T;   // 49
    int t = threadIdx.x;
    int begin = t * CH;
    int endi  = min(begin + CH, NUM_NODE);

    int sum = 0;
    for (int i = begin; i < endi; i++) sum += g_count[i];
    partial[t] = sum;
    __syncthreads();

    // Hillis-Steele inclusive scan over 1024 partials
    #pragma unroll
    for (int off = 1; off < SCAN_T; off <<= 1) {
        int v = (t >= off) ? partial[t - off] : 0;
        __syncthreads();
        partial[t] += v;
        __syncthreads();
    }

    int base = (t == 0) ? 0 : partial[t - 1];
    for (int i = begin; i < endi; i++) {
        g_off[i] = base;
        base += g_count[i];
    }
    if (t == SCAN_T - 1) g_off[NUM_NODE] = partial[SCAN_T - 1];
}

// ---------------------------------------------------------------------------
// K3: scatter packed edge meta (u, r, w) into destination buckets
// ---------------------------------------------------------------------------
__global__ void __launch_bounds__(256) scatter_kernel(
    const int*   __restrict__ edge_list,
    const float* __restrict__ edge_weight)
{
    int e = blockIdx.x * blockDim.x + threadIdx.x;
    if (e < NUM_EDGE) {
        int   u = __ldg(&edge_list[e * 3 + 0]);
        int   v = __ldg(&edge_list[e * 3 + 1]);
        int   r = __ldg(&edge_list[e * 3 + 2]);
        float w = __ldg(&edge_weight[e]);
        int pos  = atomicAdd(&g_cursor[v], 1);
        int slot = g_off[v] + pos;
        g_meta[slot] = make_int4(u, r, __float_as_int(w), 0);
    }
}

// ---------------------------------------------------------------------------
// K4: per-node gather-reduce + variance update (no atomics!)
// 16 lanes per node, each lane owns a float4 of the 64-dim row.
// 2 nodes per warp, 16 nodes per 256-thread block.
// ---------------------------------------------------------------------------
__global__ void __launch_bounds__(256) gather_kernel(
    const float* __restrict__ input,
    const float* __restrict__ boundary,
    const float* __restrict__ relw)
{
    int tid  = blockIdx.x * blockDim.x + threadIdx.x;
    int grp  = tid >> 4;           // 16-lane group id == node id
    int sub  = tid & 15;           // float4 index within 64-dim row
    if (grp >= NUM_NODE) return;
    int n = grp;

    int start = __ldg(&g_off[n]);
    int end   = __ldg(&g_off[n + 1]);

    float4 bb = __ldg((const float4*)(boundary + (size_t)n * DIM) + sub);
    float4 s  = bb;
    float4 q  = make_float4(bb.x * bb.x, bb.y * bb.y, bb.z * bb.z, bb.w * bb.w);

    // software-pipelined: prefetch next meta while gathering current
    int4 m = (start < end) ? __ldg(&g_meta[start]) : make_int4(0, 0, 0, 0);
    for (int i = start; i < end; i++) {
        int4 mn = (i + 1 < end) ? __ldg(&g_meta[i + 1]) : m;

        float w   = __int_as_float(m.z);
        float4 x  = __ldg((const float4*)(input + (size_t)m.x * DIM) + sub);
        float4 rr = __ldg((const float4*)(relw  + (size_t)m.y * DIM) + sub);

        float4 msg;
        msg.x = x.x * rr.x * w;
        msg.y = x.y * rr.y * w;
        msg.z = x.z * rr.z * w;
        msg.w = x.w * rr.w * w;

        s.x += msg.x; s.y += msg.y; s.z += msg.z; s.w += msg.w;
        q.x += msg.x * msg.x; q.y += msg.y * msg.y;
        q.z += msg.z * msg.z; q.w += msg.w * msg.w;

        m = mn;
    }

    float deg = (float)(end - start);
    float inv = 1.0f / (deg + 1.0f);

    float4 u4;
    {
        float sm;
        sm   = s.x * inv; u4.x = sqrtf(fmaxf(q.x * inv - sm * sm, 1e-6f));
        sm   = s.y * inv; u4.y = sqrtf(fmaxf(q.y * inv - sm * sm, 1e-6f));
        sm   = s.z * inv; u4.z = sqrtf(fmaxf(q.z * inv - sm * sm, 1e-6f));
        sm   = s.w * inv; u4.w = sqrtf(fmaxf(q.w * inv - sm * sm, 1e-6f));
    }
    *((float4*)(g_u + (size_t)n * DIM) + sub) = u4;
}

// ---------------------------------------------------------------------------
// K5: 64x64 GEMM epilogue: out = u @ W^T + b
// Block = 256 threads, tile of 64 nodes.
// ---------------------------------------------------------------------------
__global__ void __launch_bounds__(256) gemm_kernel(
    const float* __restrict__ W,
    const float* __restrict__ b,
    float* __restrict__ out)
{
    __shared__ float Wsh[DIM * DIM];         // Wsh[d*64 + j] = W[j*64 + d]
    __shared__ float Ush[64 * (DIM + 1)];    // padded stride 65
    __shared__ float bsh[DIM];

    int tid = threadIdx.x;

    for (int i = tid; i < DIM * DIM; i += 256) {
        int j = i >> 6, d = i & 63;
        Wsh[d * DIM + j] = W[i];
    }
    if (tid < DIM) bsh[tid] = b[tid];

    int n0 = blockIdx.x * 64;

    for (int i = tid; i < 64 * DIM; i += 256) {
        int nl = i >> 6, d = i & 63;
        int n  = n0 + nl;
        float u = (n < NUM_NODE) ? g_u[(size_t)n0 * DIM + i] : 0.0f;
        Ush[nl * (DIM + 1) + d] = u;
    }
    __syncthreads();

    int nl = tid >> 2;
    int j0 = (tid & 3) * 16;

    float acc[16];
    #pragma unroll
    for (int k = 0; k < 16; k++) acc[k] = bsh[j0 + k];

    #pragma unroll 4
    for (int d = 0; d < DIM; d++) {
        float u = Ush[nl * (DIM + 1) + d];
        const float4* wrow = (const float4*)&Wsh[d * DIM + j0];
        float4 w0 = wrow[0];
        float4 w1 = wrow[1];
        float4 w2 = wrow[2];
        float4 w3 = wrow[3];
        acc[0]  += u * w0.x;  acc[1]  += u * w0.y;
        acc[2]  += u * w0.z;  acc[3]  += u * w0.w;
        acc[4]  += u * w1.x;  acc[5]  += u * w1.y;
        acc[6]  += u * w1.z;  acc[7]  += u * w1.w;
        acc[8]  += u * w2.x;  acc[9]  += u * w2.y;
        acc[10] += u * w2.z;  acc[11] += u * w2.w;
        acc[12] += u * w3.x;  acc[13] += u * w3.y;
        acc[14] += u * w3.z;  acc[15] += u * w3.w;
    }

    int n = n0 + nl;
    if (n < NUM_NODE) {
        float4* op = (float4*)(out + (size_t)n * DIM + j0);
        op[0] = make_float4(acc[0],  acc[1],  acc[2],  acc[3]);
        op[1] = make_float4(acc[4],  acc[5],  acc[6],  acc[7]);
        op[2] = make_float4(acc[8],  acc[9],  acc[10], acc[11]);
        op[3] = make_float4(acc[12], acc[13], acc[14], acc[15]);
    }
}

// ---------------------------------------------------------------------------
// Launch
// Inputs (metadata order): input, boundary, edge_list, edge_weight,
//                          relation_weight, W, b
// ---------------------------------------------------------------------------
extern "C" void kernel_launch(void* const* d_in, const int* in_sizes, int n_in,
                              void* d_out, int out_size)
{
    const float* input    = (const float*)d_in[0];
    const float* boundary = (const float*)d_in[1];
    const int*   edges    = (const int*)  d_in[2];
    const float* eweight  = (const float*)d_in[3];
    const float* relw     = (const float*)d_in[4];
    const float* W        = (const float*)d_in[5];
    const float* b        = (const float*)d_in[6];
    float*       out      = (float*)d_out;

    zero_kernel<<<(NUM_NODE + 255) / 256, 256>>>();
    hist_kernel<<<(NUM_EDGE + 255) / 256, 256>>>(edges);
    scan_kernel<<<1, SCAN_T>>>();
    scatter_kernel<<<(NUM_EDGE + 255) / 256, 256>>>(edges, eweight);

    {
        // 16 lanes per node, 16 nodes per 256-thread block
        int blocks = (NUM_NODE * 16 + 255) / 256;
        gather_kernel<<<blocks, 256>>>(input, boundary, relw);
    }
    gemm_kernel<<<(NUM_NODE + 63) / 64, 256>>>(W, b, out);
}

// round 6
// speedup vs baseline: 1.5164x; 1.5164x over previous
#include <cuda_runtime.h>
#include <cstdint>

#define NUM_NODE 50000
#define NUM_EDGE 1600000
#define NUM_REL  512
#define DIM      64
#define SCAN_T   1024

// ---------------------------------------------------------------------------
// Device scratch (alloc-free rule: __device__ globals)
// ---------------------------------------------------------------------------
__device__ int   g_count[NUM_NODE];
__device__ int   g_off[NUM_NODE + 1];
__device__ int   g_pos[NUM_EDGE];         // intra-bucket position per edge
__device__ int4  g_meta[NUM_EDGE];        // (u, r, w_bits, pad) per bucket slot
__device__ float g_u[NUM_NODE * DIM];     // sqrt-variance staged for GEMM

// ---------------------------------------------------------------------------
// K0: zero counters
// ---------------------------------------------------------------------------
__global__ void zero_kernel() {
    int i = blockIdx.x * blockDim.x + threadIdx.x;
    if (i < NUM_NODE) g_count[i] = 0;
}

// ---------------------------------------------------------------------------
// K1: histogram of destination nodes + record per-edge bucket position
// ---------------------------------------------------------------------------
__global__ void __launch_bounds__(256) hist_kernel(const int* __restrict__ edge_list) {
    int e = blockIdx.x * blockDim.x + threadIdx.x;
    if (e < NUM_EDGE) {
        int v = __ldg(&edge_list[e * 3 + 1]);
        g_pos[e] = atomicAdd(&g_count[v], 1);
    }
}

// ---------------------------------------------------------------------------
// K2: single-block exclusive scan over 50K counts -> offsets
// ---------------------------------------------------------------------------
__global__ void __launch_bounds__(SCAN_T) scan_kernel() {
    __shared__ int partial[SCAN_T];
    const int CH = (NUM_NODE + SCAN_T - 1) / SCAN_T;   // 49
    int t = threadIdx.x;
    int begin = t * CH;
    int endi  = min(begin + CH, NUM_NODE);

    int sum = 0;
    for (int i = begin; i < endi; i++) sum += g_count[i];
    partial[t] = sum;
    __syncthreads();

    #pragma unroll
    for (int off = 1; off < SCAN_T; off <<= 1) {
        int v = (t >= off) ? partial[t - off] : 0;
        __syncthreads();
        partial[t] += v;
        __syncthreads();
    }

    int base = (t == 0) ? 0 : partial[t - 1];
    for (int i = begin; i < endi; i++) {
        g_off[i] = base;
        base += g_count[i];
    }
    if (t == SCAN_T - 1) g_off[NUM_NODE] = partial[SCAN_T - 1];
}

// ---------------------------------------------------------------------------
// K3: scatter packed edge meta into buckets — atomic-free, full MLP
// ---------------------------------------------------------------------------
__global__ void __launch_bounds__(256) scatter_kernel(
    const int*   __restrict__ edge_list,
    const float* __restrict__ edge_weight)
{
    int e = blockIdx.x * blockDim.x + threadIdx.x;
    if (e < NUM_EDGE) {
        int   u   = __ldg(&edge_list[e * 3 + 0]);
        int   v   = __ldg(&edge_list[e * 3 + 1]);
        int   r   = __ldg(&edge_list[e * 3 + 2]);
        float w   = __ldg(&edge_weight[e]);
        int   pos = g_pos[e];
        int  slot = __ldg(&g_off[v]) + pos;
        g_meta[slot] = make_int4(u, r, __float_as_int(w), 0);
    }
}

// ---------------------------------------------------------------------------
// K4: per-node gather-reduce + variance update, unrolled x4 for MLP.
// 16 lanes per node (each lane owns one float4 of the 64-dim row).
// ---------------------------------------------------------------------------
__global__ void __launch_bounds__(256) gather_kernel(
    const float* __restrict__ input,
    const float* __restrict__ boundary,
    const float* __restrict__ relw)
{
    int tid  = blockIdx.x * blockDim.x + threadIdx.x;
    int n    = tid >> 4;           // node id
    int sub  = tid & 15;           // float4 index within 64-dim row
    if (n >= NUM_NODE) return;

    int start = __ldg(&g_off[n]);
    int end   = __ldg(&g_off[n + 1]);

    float4 bb = __ldg((const float4*)(boundary + (size_t)n * DIM) + sub);
    float4 s  = bb;
    float4 q  = make_float4(bb.x * bb.x, bb.y * bb.y, bb.z * bb.z, bb.w * bb.w);

    int i = start;

    // Main unrolled loop: 4 independent edge pipelines -> 12 outstanding loads
    for (; i + 4 <= end; i += 4) {
        int4 m0 = __ldg(&g_meta[i + 0]);
        int4 m1 = __ldg(&g_meta[i + 1]);
        int4 m2 = __ldg(&g_meta[i + 2]);
        int4 m3 = __ldg(&g_meta[i + 3]);

        float4 x0 = __ldg((const float4*)(input + (size_t)m0.x * DIM) + sub);
        float4 x1 = __ldg((const float4*)(input + (size_t)m1.x * DIM) + sub);
        float4 x2 = __ldg((const float4*)(input + (size_t)m2.x * DIM) + sub);
        float4 x3 = __ldg((const float4*)(input + (size_t)m3.x * DIM) + sub);

        float4 r0 = __ldg((const float4*)(relw + (size_t)m0.y * DIM) + sub);
        float4 r1 = __ldg((const float4*)(relw + (size_t)m1.y * DIM) + sub);
        float4 r2 = __ldg((const float4*)(relw + (size_t)m2.y * DIM) + sub);
        float4 r3 = __ldg((const float4*)(relw + (size_t)m3.y * DIM) + sub);

        float w0 = __int_as_float(m0.z);
        float w1 = __int_as_float(m1.z);
        float w2 = __int_as_float(m2.z);
        float w3 = __int_as_float(m3.z);

        float4 a0, a1, a2, a3;
        a0.x = x0.x * r0.x * w0; a0.y = x0.y * r0.y * w0;
        a0.z = x0.z * r0.z * w0; a0.w = x0.w * r0.w * w0;
        a1.x = x1.x * r1.x * w1; a1.y = x1.y * r1.y * w1;
        a1.z = x1.z * r1.z * w1; a1.w = x1.w * r1.w * w1;
        a2.x = x2.x * r2.x * w2; a2.y = x2.y * r2.y * w2;
        a2.z = x2.z * r2.z * w2; a2.w = x2.w * r2.w * w2;
        a3.x = x3.x * r3.x * w3; a3.y = x3.y * r3.y * w3;
        a3.z = x3.z * r3.z * w3; a3.w = x3.w * r3.w * w3;

        s.x += a0.x + a1.x + a2.x + a3.x;
        s.y += a0.y + a1.y + a2.y + a3.y;
        s.z += a0.z + a1.z + a2.z + a3.z;
        s.w += a0.w + a1.w + a2.w + a3.w;

        q.x += a0.x * a0.x + a1.x * a1.x + a2.x * a2.x + a3.x * a3.x;
        q.y += a0.y * a0.y + a1.y * a1.y + a2.y * a2.y + a3.y * a3.y;
        q.z += a0.z * a0.z + a1.z * a1.z + a2.z * a2.z + a3.z * a3.z;
        q.w += a0.w * a0.w + a1.w * a1.w + a2.w * a2.w + a3.w * a3.w;
    }

    // Remainder
    for (; i < end; i++) {
        int4 m = __ldg(&g_meta[i]);
        float w   = __int_as_float(m.z);
        float4 x  = __ldg((const float4*)(input + (size_t)m.x * DIM) + sub);
        float4 rr = __ldg((const float4*)(relw  + (size_t)m.y * DIM) + sub);
        float4 a;
        a.x = x.x * rr.x * w; a.y = x.y * rr.y * w;
        a.z = x.z * rr.z * w; a.w = x.w * rr.w * w;
        s.x += a.x; s.y += a.y; s.z += a.z; s.w += a.w;
        q.x += a.x * a.x; q.y += a.y * a.y;
        q.z += a.z * a.z; q.w += a.w * a.w;
    }

    float deg = (float)(end - start);
    float inv = 1.0f / (deg + 1.0f);

    float4 u4;
    float sm;
    sm = s.x * inv; u4.x = sqrtf(fmaxf(q.x * inv - sm * sm, 1e-6f));
    sm = s.y * inv; u4.y = sqrtf(fmaxf(q.y * inv - sm * sm, 1e-6f));
    sm = s.z * inv; u4.z = sqrtf(fmaxf(q.z * inv - sm * sm, 1e-6f));
    sm = s.w * inv; u4.w = sqrtf(fmaxf(q.w * inv - sm * sm, 1e-6f));

    *((float4*)(g_u + (size_t)n * DIM) + sub) = u4;
}

// ---------------------------------------------------------------------------
// K5: 64x64 GEMM epilogue: out = u @ W^T + b
// ---------------------------------------------------------------------------
__global__ void __launch_bounds__(256) gemm_kernel(
    const float* __restrict__ W,
    const float* __restrict__ b,
    float* __restrict__ out)
{
    __shared__ float Wsh[DIM * DIM];         // Wsh[d*64 + j] = W[j*64 + d]
    __shared__ float Ush[64 * (DIM + 1)];    // padded stride 65
    __shared__ float bsh[DIM];

    int tid = threadIdx.x;

    for (int i = tid; i < DIM * DIM; i += 256) {
        int j = i >> 6, d = i & 63;
        Wsh[d * DIM + j] = W[i];
    }
    if (tid < DIM) bsh[tid] = b[tid];

    int n0 = blockIdx.x * 64;

    for (int i = tid; i < 64 * DIM; i += 256) {
        int nl = i >> 6, d = i & 63;
        int n  = n0 + nl;
        float u = (n < NUM_NODE) ? g_u[(size_t)n0 * DIM + i] : 0.0f;
        Ush[nl * (DIM + 1) + d] = u;
    }
    __syncthreads();

    int nl = tid >> 2;
    int j0 = (tid & 3) * 16;

    float acc[16];
    #pragma unroll
    for (int k = 0; k < 16; k++) acc[k] = bsh[j0 + k];

    #pragma unroll 4
    for (int d = 0; d < DIM; d++) {
        float u = Ush[nl * (DIM + 1) + d];
        const float4* wrow = (const float4*)&Wsh[d * DIM + j0];
        float4 w0 = wrow[0];
        float4 w1 = wrow[1];
        float4 w2 = wrow[2];
        float4 w3 = wrow[3];
        acc[0]  += u * w0.x;  acc[1]  += u * w0.y;
        acc[2]  += u * w0.z;  acc[3]  += u * w0.w;
        acc[4]  += u * w1.x;  acc[5]  += u * w1.y;
        acc[6]  += u * w1.z;  acc[7]  += u * w1.w;
        acc[8]  += u * w2.x;  acc[9]  += u * w2.y;
        acc[10] += u * w2.z;  acc[11] += u * w2.w;
        acc[12] += u * w3.x;  acc[13] += u * w3.y;
        acc[14] += u * w3.z;  acc[15] += u * w3.w;
    }

    int n = n0 + nl;
    if (n < NUM_NODE) {
        float4* op = (float4*)(out + (size_t)n * DIM + j0);
        op[0] = make_float4(acc[0],  acc[1],  acc[2],  acc[3]);
        op[1] = make_float4(acc[4],  acc[5],  acc[6],  acc[7]);
        op[2] = make_float4(acc[8],  acc[9],  acc[10], acc[11]);
        op[3] = make_float4(acc[12], acc[13], acc[14], acc[15]);
    }
}

// ---------------------------------------------------------------------------
// Launch
// Inputs (metadata order): input, boundary, edge_list, edge_weight,
//                          relation_weight, W, b
// ---------------------------------------------------------------------------
extern "C" void kernel_launch(void* const* d_in, const int* in_sizes, int n_in,
                              void* d_out, int out_size)
{
    const float* input    = (const float*)d_in[0];
    const float* boundary = (const float*)d_in[1];
    const int*   edges    = (const int*)  d_in[2];
    const float* eweight  = (const float*)d_in[3];
    const float* relw     = (const float*)d_in[4];
    const float* W        = (const float*)d_in[5];
    const float* b        = (const float*)d_in[6];
    float*       out      = (float*)d_out;

    zero_kernel<<<(NUM_NODE + 255) / 256, 256>>>();
    hist_kernel<<<(NUM_EDGE + 255) / 256, 256>>>(edges);
    scan_kernel<<<1, SCAN_T>>>();
    scatter_kernel<<<(NUM_EDGE + 255) / 256, 256>>>(edges, eweight);

    gather_kernel<<<(NUM_NODE * 16 + 255) / 256, 256>>>(input, boundary, relw);
    gemm_kernel<<<(NUM_NODE + 63) / 64, 256>>>(W, b, out);
}